// round 3
// baseline (speedup 1.0000x reference)
#include <cuda_runtime.h>
#include <math.h>

// LIF cell scan: v = v*sigmoid(decay)*(1-z) + x_t ; z = (v - 0.5 > 0)
// x [B,T,H] f32 -> spikes [B,T,H] f32.  B=512, T=512, H=256.
//
// One thread per (b,h) chain, sequential over T. Pure HBM streaming
// (256MB read + 256MB write). R3: software-pipelined chunk loads (loads for
// chunk k+1 in flight during chunk k's serial recurrence) + 1024x128 launch
// for wave balance.

#define B_DIM 512
#define T_DIM 512
#define H_DIM 256
#define UNROLL 16

__global__ __launch_bounds__(128, 8)
void lif_scan_kernel(const float* __restrict__ x,
                     const float* __restrict__ decay,
                     const float* __restrict__ v0,
                     const float* __restrict__ z0,
                     float* __restrict__ out)
{
    const int b = blockIdx.x >> 1;                       // 0..511
    const int h = ((blockIdx.x & 1) << 7) + threadIdx.x; // 0..255, warp-contiguous

    // sigmoid(decay[h]) once per thread, correctly rounded via fp64
    const float d = (float)(1.0 / (1.0 + exp(-(double)decay[h])));

    const int bh = b * H_DIM + h;
    float v = v0[bh];
    float z = z0[bh];

    const size_t base = (size_t)b * T_DIM * H_DIM + h;
    const float* __restrict__ xp = x + base;
    float* __restrict__ op = out + base;

    // Two named register buffers (dynamic-indexed buffer would spill).
    float xa[UNROLL], xb[UNROLL];

    // Prologue: loads for chunk 0
    #pragma unroll
    for (int i = 0; i < UNROLL; i++)
        xa[i] = __ldcs(xp + (size_t)i * H_DIM);

    #pragma unroll 1
    for (int t = 0; t < T_DIM; t += 2 * UNROLL) {
        // Prefetch chunk B (t+U) — always valid (t+U <= 496 < 512)
        #pragma unroll
        for (int i = 0; i < UNROLL; i++)
            xb[i] = __ldcs(xp + (size_t)(t + UNROLL + i) * H_DIM);

        // Compute + store chunk A from xa (loads for xb now in flight)
        #pragma unroll
        for (int i = 0; i < UNROLL; i++) {
            // (1 - z) is exactly 0.0f or 1.0f -> rounding matches reference
            v = v * d * (1.0f - z) + xa[i];
            z = (v > 0.5f) ? 1.0f : 0.0f;
            __stcs(op + (size_t)(t + i) * H_DIM, z);
        }

        // Prefetch next chunk A (t+2U), except on last outer iteration
        if (t + 2 * UNROLL < T_DIM) {
            #pragma unroll
            for (int i = 0; i < UNROLL; i++)
                xa[i] = __ldcs(xp + (size_t)(t + 2 * UNROLL + i) * H_DIM);
        }

        // Compute + store chunk B from xb
        #pragma unroll
        for (int i = 0; i < UNROLL; i++) {
            v = v * d * (1.0f - z) + xb[i];
            z = (v > 0.5f) ? 1.0f : 0.0f;
            __stcs(op + (size_t)(t + UNROLL + i) * H_DIM, z);
        }
    }
}

extern "C" void kernel_launch(void* const* d_in, const int* in_sizes, int n_in,
                              void* d_out, int out_size)
{
    // Bind inputs BY SIZE (robust to metadata ordering):
    //   x: B*T*H   decay: H   v0,z0: B*H (both zero at runtime; order harmless)
    const float* x = 0;
    const float* decay = 0;
    const float* v0 = 0;
    const float* z0 = 0;

    const long long n_x  = (long long)B_DIM * T_DIM * H_DIM;
    const long long n_bh = (long long)B_DIM * H_DIM;

    for (int i = 0; i < n_in; i++) {
        long long n = in_sizes[i];
        if (n == n_x) {
            x = (const float*)d_in[i];
        } else if (n == H_DIM) {
            decay = (const float*)d_in[i];
        } else if (n == n_bh) {
            if (!v0) v0 = (const float*)d_in[i];
            else     z0 = (const float*)d_in[i];
        }
    }
    if (!x || !decay || !v0 || !z0) return;

    float* out = (float*)d_out;

    lif_scan_kernel<<<B_DIM * 2, 128>>>(x, decay, v0, z0, out);
}

// round 6
// speedup vs baseline: 1.0720x; 1.0720x over previous
#include <cuda_runtime.h>
#include <math.h>

// LIF cell scan: v = v*sigmoid(decay)*(1-z) + x_t ; z = (v - 0.5 > 0)
// x [B,T,H] f32 -> spikes [B,T,H] f32.  B=512, T=512, H=256.
//
// R6: float4 vectorization — each thread owns 4 consecutive h-chains.
// 32,768 threads (1024 blocks x 32), LDG.128/STG.128, 4-way ILP in the
// recurrence, double-buffered 8-deep prefetch (2*DEPTH divides T exactly,
// so every prefetch is statically in range). Exact same arithmetic
// association as the rel_err=0 scalar version.

#define B_DIM 512
#define T_DIM 512
#define H_DIM 256
#define HQ    (H_DIM / 4)   // 64 float4 per (b,t) row
#define DEPTH 8             // 2*DEPTH = 16 divides T_DIM = 512

__global__ __launch_bounds__(32)
void lif_scan4_kernel(const float4* __restrict__ x,
                      const float4* __restrict__ decay,
                      const float4* __restrict__ v0,
                      const float4* __restrict__ z0,
                      float4* __restrict__ out)
{
    const int b = blockIdx.x >> 1;                        // 0..511
    const int q = ((blockIdx.x & 1) << 5) + threadIdx.x;  // float4 index in row: 0..63

    // sigmoid(decay) once per chain, correctly rounded via fp64
    const float4 dc = decay[q];
    float4 d;
    d.x = (float)(1.0 / (1.0 + exp(-(double)dc.x)));
    d.y = (float)(1.0 / (1.0 + exp(-(double)dc.y)));
    d.z = (float)(1.0 / (1.0 + exp(-(double)dc.z)));
    d.w = (float)(1.0 / (1.0 + exp(-(double)dc.w)));

    const int bh = b * HQ + q;
    float4 v = v0[bh];
    float4 z = z0[bh];

    const size_t base = (size_t)b * T_DIM * HQ + q;
    const float4* __restrict__ xp = x + base;
    float4* __restrict__ op = out + base;

    float4 xa[DEPTH], xb[DEPTH];

    // Prologue: chunk 0 (t = 0..7)
    #pragma unroll
    for (int i = 0; i < DEPTH; i++)
        xa[i] = __ldcs(xp + (size_t)i * HQ);

    #pragma unroll 1
    for (int t = 0; t < T_DIM; t += 2 * DEPTH) {
        // Prefetch chunk B (t+8..t+15) — always in range since 16 | 512
        #pragma unroll
        for (int i = 0; i < DEPTH; i++)
            xb[i] = __ldcs(xp + (size_t)(t + DEPTH + i) * HQ);

        // Compute + store chunk A. (1-z) is exactly 0.0f or 1.0f -> rounding
        // matches the reference association exactly.
        #pragma unroll
        for (int i = 0; i < DEPTH; i++) {
            float4 xv = xa[i];
            v.x = v.x * d.x * (1.0f - z.x) + xv.x;
            v.y = v.y * d.y * (1.0f - z.y) + xv.y;
            v.z = v.z * d.z * (1.0f - z.z) + xv.z;
            v.w = v.w * d.w * (1.0f - z.w) + xv.w;
            z.x = (v.x > 0.5f) ? 1.0f : 0.0f;
            z.y = (v.y > 0.5f) ? 1.0f : 0.0f;
            z.z = (v.z > 0.5f) ? 1.0f : 0.0f;
            z.w = (v.w > 0.5f) ? 1.0f : 0.0f;
            __stcs(op + (size_t)(t + i) * HQ, z);
        }

        // Prefetch next chunk A (t+16..t+23), except on the final iteration
        if (t + 2 * DEPTH < T_DIM) {
            #pragma unroll
            for (int i = 0; i < DEPTH; i++)
                xa[i] = __ldcs(xp + (size_t)(t + 2 * DEPTH + i) * HQ);
        }

        // Compute + store chunk B
        #pragma unroll
        for (int i = 0; i < DEPTH; i++) {
            float4 xv = xb[i];
            v.x = v.x * d.x * (1.0f - z.x) + xv.x;
            v.y = v.y * d.y * (1.0f - z.y) + xv.y;
            v.z = v.z * d.z * (1.0f - z.z) + xv.z;
            v.w = v.w * d.w * (1.0f - z.w) + xv.w;
            z.x = (v.x > 0.5f) ? 1.0f : 0.0f;
            z.y = (v.y > 0.5f) ? 1.0f : 0.0f;
            z.z = (v.z > 0.5f) ? 1.0f : 0.0f;
            z.w = (v.w > 0.5f) ? 1.0f : 0.0f;
            __stcs(op + (size_t)(t + DEPTH + i) * HQ, z);
        }
    }
}

extern "C" void kernel_launch(void* const* d_in, const int* in_sizes, int n_in,
                              void* d_out, int out_size)
{
    // Bind inputs BY SIZE (robust to metadata ordering):
    //   x: B*T*H   decay: H   v0,z0: B*H (both zero at runtime; order harmless)
    const float* x = 0;
    const float* decay = 0;
    const float* v0 = 0;
    const float* z0 = 0;

    const long long n_x  = (long long)B_DIM * T_DIM * H_DIM;
    const long long n_bh = (long long)B_DIM * H_DIM;

    for (int i = 0; i < n_in; i++) {
        long long n = in_sizes[i];
        if (n == n_x) {
            x = (const float*)d_in[i];
        } else if (n == H_DIM) {
            decay = (const float*)d_in[i];
        } else if (n == n_bh) {
            if (!v0) v0 = (const float*)d_in[i];
            else     z0 = (const float*)d_in[i];
        }
    }
    if (!x || !decay || !v0 || !z0) return;

    lif_scan4_kernel<<<B_DIM * 2, 32>>>(
        (const float4*)x, (const float4*)decay,
        (const float4*)v0, (const float4*)z0,
        (float4*)d_out);
}